// round 14
// baseline (speedup 1.0000x reference)
#include <cuda_runtime.h>
#include <cstdint>

// LQE_17841294147886 — fused softmax/top4/MLP/broadcast-add
// R12: fully warp-local tiles. Quad softmax (scalar CF LDS, no masks),
//      in-warp MLP (2pos x 8rows), per-warp out chunks -> ONE barrier/tile
//      (was 3). Double-buffered cp.async pipeline unchanged (76.5us base).

#define TPB        128
#define NBINS      33
#define DPOS       132
#define TILE_POS   32
#define NTILES     4
#define BUF_FLOATS (TILE_POS * DPOS)      // 4224 per buffer
#define STAT_ROW   20
#define WROW       20
#define NCOUT      80
#define LOG2E      1.4426950408889634f

typedef unsigned long long u64;

__device__ __forceinline__ u64 fma2(u64 a, u64 b, u64 c) {
    u64 d; asm("fma.rn.f32x2 %0, %1, %2, %3;" : "=l"(d) : "l"(a), "l"(b), "l"(c));
    return d;
}
__device__ __forceinline__ u64 addf2(u64 a, u64 b) {
    u64 d; asm("add.rn.f32x2 %0, %1, %2;" : "=l"(d) : "l"(a), "l"(b));
    return d;
}
__device__ __forceinline__ void unpack2(u64 v, float& lo, float& hi) {
    asm("mov.b64 {%0, %1}, %2;" : "=f"(lo), "=f"(hi) : "l"(v));
}
__device__ __forceinline__ float ex2f(float x) {
    float r; asm("ex2.approx.f32 %0, %1;" : "=f"(r) : "f"(x));
    return r;
}
__device__ __forceinline__ float rcpf(float x) {
    float r; asm("rcp.approx.f32 %0, %1;" : "=f"(r) : "f"(x));
    return r;
}
__device__ __forceinline__ void cp16(uint32_t dst, const void* src) {
    asm volatile("cp.async.cg.shared.global [%0], [%1], 16;"
                 :: "r"(dst), "l"(src));
}
#define CP_COMMIT() asm volatile("cp.async.commit_group;" ::: "memory")
#define CP_WAIT0()  asm volatile("cp.async.wait_group 0;" ::: "memory")

// sort 4 floats descending: 10 ops
__device__ __forceinline__ void sort4(float x0, float x1, float x2, float x3,
                                      float& a, float& b, float& c, float& d) {
    float p = fmaxf(x0, x1), q = fminf(x0, x1);
    float r = fmaxf(x2, x3), s = fminf(x2, x3);
    a = fmaxf(p, r); float tt = fminf(p, r);
    d = fminf(q, s); float u  = fmaxf(q, s);
    b = fmaxf(tt, u); c = fminf(tt, u);
}
// merge sorted-desc R with sorted-desc A -> top4 desc in R: 12 ops
__device__ __forceinline__ void merge4(float& r0, float& r1, float& r2, float& r3,
                                       float a0, float a1, float a2, float a3) {
    float L0 = fmaxf(r0, a3), L1 = fmaxf(r1, a2);
    float L2 = fmaxf(r2, a1), L3 = fmaxf(r3, a0);
    float m0 = fmaxf(L0, L2), m2 = fminf(L0, L2);
    float m1 = fmaxf(L1, L3), m3 = fminf(L1, L3);
    r0 = fmaxf(m0, m1); r1 = fminf(m0, m1);
    r2 = fmaxf(m2, m3); r3 = fminf(m2, m3);
}
// insert e into sorted-desc top4: 7 ops
__device__ __forceinline__ void top4_push(float e, float& t0, float& t1,
                                          float& t2, float& t3) {
    float c0 = fminf(t0, e);  t0 = fmaxf(t0, e);
    float c1 = fminf(t1, c0); t1 = fmaxf(t1, c0);
    float c2 = fminf(t2, c1); t2 = fmaxf(t2, c1);
    t3 = fmaxf(t3, c2);
}

__global__ __launch_bounds__(TPB, 5)
void lqe_kernel(const float* __restrict__ scores,
                const float* __restrict__ pred,
                const float* __restrict__ w1,
                const float* __restrict__ b1,
                const float* __restrict__ w2,
                const float* __restrict__ b2,
                float* __restrict__ out)
{
    extern __shared__ float smem[];
    float* buf0 = smem;                               // [32][132] tile buffer A
    float* buf1 = smem + BUF_FLOATS;                  // [32][132] tile buffer B
    float* stat = smem + 2 * BUF_FLOATS;              // [32][20] packed stats
    float* wsm  = stat + TILE_POS * STAT_ROW;         // [64][20] folded weights
    float* qs   = wsm + 64 * WROW;                    // [32] per-warp q slots

    const int t  = threadIdx.x;
    const int l  = t & 31;        // lane
    const int w  = t >> 5;        // warp: owns positions w*8 .. w*8+7
    const int sm_pos = l >> 2;    // softmax: local pos in warp (0..7)
    const int sm_sid = l & 3;     // softmax: side
    const int pg = l >> 3;        // MLP: position subgroup (0..3)
    const int rg = l & 7;         // MLP: row group (0..7)
    const int blockStart = blockIdx.x * TPB;
    const float b2v = __ldg(b2);

    const uint32_t buf0u = (uint32_t)__cvta_generic_to_shared(buf0);
    const uint32_t buf1u = (uint32_t)__cvta_generic_to_shared(buf1);
    const float4* g4 = (const float4*)(pred + (size_t)blockStart * DPOS);

    // ---- prologue: start tile 0 copy into buf0 (overlaps weight build) ----
    {
        #pragma unroll
        for (int j = 0; j < 8; j++)
            cp16(buf0u + (uint32_t)(t + j * TPB) * 16u, g4 + t + j * TPB);
        if (t < 32)
            cp16(buf0u + (uint32_t)(t + 8 * TPB) * 16u, g4 + t + 8 * TPB);
        CP_COMMIT();
    }

    // ---- folded weight table: wsm[j][k] ----
    // k<16: w_eff[j][4s+i] = w1[j][5s+i] + 0.25*w1[j][5s+4]; k16=b1[j]; k17=w2[j]
    #pragma unroll
    for (int k = 0; k < (64 * WROW) / TPB; k++) {
        int f   = t + k * TPB;
        int row = f / WROW;
        int cc  = f - row * WROW;
        float v = 0.f;
        if (cc < 16) {
            int ss = cc >> 2, ii = cc & 3;
            v = __ldg(w1 + row * 20 + 5 * ss + ii)
              + 0.25f * __ldg(w1 + row * 20 + 5 * ss + 4);
        } else if (cc == 16) v = __ldg(b1 + row);
        else if (cc == 17)   v = __ldg(w2 + row);
        wsm[f] = v;
    }

    const float4* sc4 = (const float4*)scores + (size_t)blockStart * (NCOUT / 4);
    float4*       ou4 = (float4*)out          + (size_t)blockStart * (NCOUT / 4);
    // softmax row offset inside buffer (scalar reads, CF banks 4*pos+sid+k)
    const int rowOff = (w * 8 + sm_pos) * DPOS + sm_sid * NBINS;
    // out-phase base: warp chunk is 160 f4; lane starts at p0 = l/20
    const int p0 = l / 20;
    const int r0 = l - p0 * 20;

    #pragma unroll
    for (int tau = 0; tau < NTILES; tau++) {
        CP_WAIT0();
        __syncthreads();                       // buf(tau) visible; ONLY barrier

        float* bufC = (tau & 1) ? buf1 : buf0;

        // ---- issue copy(tau+1) NOW into the other buffer (full-tile window) ----
        if (tau < NTILES - 1) {
            uint32_t dstu = (tau & 1) ? buf0u : buf1u;
            const float4* gt = g4 + (tau + 1) * (TILE_POS * NBINS);
            #pragma unroll
            for (int j = 0; j < 8; j++)
                cp16(dstu + (uint32_t)(t + j * TPB) * 16u, gt + t + j * TPB);
            if (t < 32)
                cp16(dstu + (uint32_t)(t + 8 * TPB) * 16u, gt + t + 8 * TPB);
            CP_COMMIT();
        }

        // ---- prefetch this tile's scores for the warp's own chunk ----
        const int cBase = tau * 640 + w * 160;
        float4 rs0 = sc4[cBase + l];
        float4 rs1 = sc4[cBase + l + 32];
        float4 rs2 = sc4[cBase + l + 64];
        float4 rs3 = sc4[cBase + l + 96];
        float4 rs4 = sc4[cBase + l + 128];

        // ---- softmax + top4: quad mapping, 33 scalar CF LDS, no masks ----
        {
            const float* x = bufC + rowOff;
            float r0s, r1s, r2s, r3s;
            float sum0, sum1;
            {
                float e0 = ex2f(x[0] * LOG2E);
                float e1 = ex2f(x[1] * LOG2E);
                float e2 = ex2f(x[2] * LOG2E);
                float e3 = ex2f(x[3] * LOG2E);
                sum0 = e0 + e2; sum1 = e1 + e3;
                sort4(e0, e1, e2, e3, r0s, r1s, r2s, r3s);
            }
            #pragma unroll
            for (int g = 1; g < 8; g++) {
                float e0 = ex2f(x[4 * g + 0] * LOG2E);
                float e1 = ex2f(x[4 * g + 1] * LOG2E);
                float e2 = ex2f(x[4 * g + 2] * LOG2E);
                float e3 = ex2f(x[4 * g + 3] * LOG2E);
                sum0 += e0 + e2; sum1 += e1 + e3;
                float a0, a1, a2, a3;
                sort4(e0, e1, e2, e3, a0, a1, a2, a3);
                merge4(r0s, r1s, r2s, r3s, a0, a1, a2, a3);
            }
            {
                float e = ex2f(x[32] * LOG2E);
                sum0 += e;
                top4_push(e, r0s, r1s, r2s, r3s);
            }
            float inv = rcpf(sum0 + sum1);
            *(float4*)(stat + (w * 8 + sm_pos) * STAT_ROW + 4 * sm_sid) =
                make_float4(r0s * inv, r1s * inv, r2s * inv, r3s * inv);
        }
        __syncwarp();                          // stat is warp-local now

        // ---- MLP: 8 rows (j = rg + 8i) x 2 positions (w8+pg, w8+pg+4) ----
        {
            const ulonglong2* sAr =
                (const ulonglong2*)(stat + (w * 8 + pg) * STAT_ROW);
            const ulonglong2* sBr =
                (const ulonglong2*)(stat + (w * 8 + pg + 4) * STAT_ROW);
            ulonglong2 aA = sAr[0], aB = sAr[1], aC = sAr[2], aD = sAr[3];
            ulonglong2 bA = sBr[0], bB = sBr[1], bC = sBr[2], bD = sBr[3];
            float qA = 0.f, qB = 0.f;
            #pragma unroll
            for (int i = 0; i < 8; i++) {
                int j = rg + 8 * i;            // stride-80B rows: conflict-free
                const ulonglong2* wrow = (const ulonglong2*)(wsm + j * WROW);
                ulonglong2 wa = wrow[0];
                ulonglong2 wb = wrow[1];
                ulonglong2 wc2 = wrow[2];
                ulonglong2 wd = wrow[3];
                float2 bw = *(const float2*)(wsm + j * WROW + 16);

                u64 xA = fma2(wa.x, aA.x, 0ull);
                u64 yA = fma2(wc2.x, aC.x, 0ull);
                u64 xB = fma2(wa.x, bA.x, 0ull);
                u64 yB = fma2(wc2.x, bC.x, 0ull);
                xA = fma2(wa.y, aA.y, xA);  yA = fma2(wc2.y, aC.y, yA);
                xB = fma2(wa.y, bA.y, xB);  yB = fma2(wc2.y, bC.y, yB);
                xA = fma2(wb.x, aB.x, xA);  yA = fma2(wd.x, aD.x, yA);
                xB = fma2(wb.x, bB.x, xB);  yB = fma2(wd.x, bD.x, yB);
                xA = fma2(wb.y, aB.y, xA);  yA = fma2(wd.y, aD.y, yA);
                xB = fma2(wb.y, bB.y, xB);  yB = fma2(wd.y, bD.y, yB);

                u64 sA2 = addf2(xA, yA);
                u64 sB2 = addf2(xB, yB);
                float a0, a1, c0, c1;
                unpack2(sA2, a0, a1);
                unpack2(sB2, c0, c1);
                float hA = (a0 + a1) + bw.x;
                float hB = (c0 + c1) + bw.x;
                hA = fmaxf(hA, 0.f);
                hB = fmaxf(hB, 0.f);
                qA = fmaf(hA, bw.y, qA);
                qB = fmaf(hB, bw.y, qB);
            }
            qA += __shfl_xor_sync(0xffffffffu, qA, 1);
            qB += __shfl_xor_sync(0xffffffffu, qB, 1);
            qA += __shfl_xor_sync(0xffffffffu, qA, 2);
            qB += __shfl_xor_sync(0xffffffffu, qB, 2);
            qA += __shfl_xor_sync(0xffffffffu, qA, 4);
            qB += __shfl_xor_sync(0xffffffffu, qB, 4);
            if (rg == 0) {
                qs[w * 8 + pg]     = qA + b2v;
                qs[w * 8 + pg + 4] = qB + b2v;
            }
        }
        __syncwarp();                          // qs warp-local

        // ---- out-add: warp's contiguous 160-f4 chunk, coalesced ----
        {
            const float* qb = qs + w * 8;
            int pp = p0, r = r0;
            float4 v; float qv;
            qv = qb[pp]; v = rs0;
            v.x += qv; v.y += qv; v.z += qv; v.w += qv;
            ou4[cBase + l] = v;
            r += 12; pp += 1; if (r >= 20) { r -= 20; pp += 1; }
            qv = qb[pp]; v = rs1;
            v.x += qv; v.y += qv; v.z += qv; v.w += qv;
            ou4[cBase + l + 32] = v;
            r += 12; pp += 1; if (r >= 20) { r -= 20; pp += 1; }
            qv = qb[pp]; v = rs2;
            v.x += qv; v.y += qv; v.z += qv; v.w += qv;
            ou4[cBase + l + 64] = v;
            r += 12; pp += 1; if (r >= 20) { r -= 20; pp += 1; }
            qv = qb[pp]; v = rs3;
            v.x += qv; v.y += qv; v.z += qv; v.w += qv;
            ou4[cBase + l + 96] = v;
            r += 12; pp += 1; if (r >= 20) { r -= 20; pp += 1; }
            qv = qb[pp]; v = rs4;
            v.x += qv; v.y += qv; v.z += qv; v.w += qv;
            ou4[cBase + l + 128] = v;
        }
        // no further barriers: all per-tile state (stat, qs) is warp-private;
        // buf hazard is covered by the next tile's top barrier.
    }
}

extern "C" void kernel_launch(void* const* d_in, const int* in_sizes, int n_in,
                              void* d_out, int out_size)
{
    const float* scores = (const float*)d_in[0];
    const float* pred   = (const float*)d_in[1];
    const float* w1     = (const float*)d_in[2];
    const float* b1     = (const float*)d_in[3];
    const float* w2     = (const float*)d_in[4];
    const float* b2     = (const float*)d_in[5];
    // d_in[6] = k_top (fixed 4, compile-time specialized)

    int npos = in_sizes[1] / DPOS;     // 320000
    int grid = npos / TPB;             // 2500 exact

    size_t smem = (size_t)(2 * BUF_FLOATS + TILE_POS * STAT_ROW + 64 * WROW
                           + TILE_POS) * sizeof(float);
    cudaFuncSetAttribute(lqe_kernel, cudaFuncAttributeMaxDynamicSharedMemorySize,
                         (int)smem);
    lqe_kernel<<<grid, TPB, smem>>>(scores, pred, w1, b1, w2, b2, (float*)d_out);
}

// round 15
// speedup vs baseline: 1.0046x; 1.0046x over previous
#include <cuda_runtime.h>
#include <cstdint>

// LQE_17841294147886 — fused softmax/top4/MLP/broadcast-add
// R12: fully warp-local tiles. Quad softmax (scalar CF LDS, no masks),
//      in-warp MLP (2pos x 8rows), per-warp out chunks -> ONE barrier/tile
//      (was 3). Double-buffered cp.async pipeline unchanged (76.5us base).

#define TPB        128
#define NBINS      33
#define DPOS       132
#define TILE_POS   32
#define NTILES     4
#define BUF_FLOATS (TILE_POS * DPOS)      // 4224 per buffer
#define STAT_ROW   20
#define WROW       20
#define NCOUT      80
#define LOG2E      1.4426950408889634f

typedef unsigned long long u64;

__device__ __forceinline__ u64 fma2(u64 a, u64 b, u64 c) {
    u64 d; asm("fma.rn.f32x2 %0, %1, %2, %3;" : "=l"(d) : "l"(a), "l"(b), "l"(c));
    return d;
}
__device__ __forceinline__ u64 addf2(u64 a, u64 b) {
    u64 d; asm("add.rn.f32x2 %0, %1, %2;" : "=l"(d) : "l"(a), "l"(b));
    return d;
}
__device__ __forceinline__ void unpack2(u64 v, float& lo, float& hi) {
    asm("mov.b64 {%0, %1}, %2;" : "=f"(lo), "=f"(hi) : "l"(v));
}
__device__ __forceinline__ float ex2f(float x) {
    float r; asm("ex2.approx.f32 %0, %1;" : "=f"(r) : "f"(x));
    return r;
}
__device__ __forceinline__ float rcpf(float x) {
    float r; asm("rcp.approx.f32 %0, %1;" : "=f"(r) : "f"(x));
    return r;
}
__device__ __forceinline__ void cp16(uint32_t dst, const void* src) {
    asm volatile("cp.async.cg.shared.global [%0], [%1], 16;"
                 :: "r"(dst), "l"(src));
}
#define CP_COMMIT() asm volatile("cp.async.commit_group;" ::: "memory")
#define CP_WAIT0()  asm volatile("cp.async.wait_group 0;" ::: "memory")

// sort 4 floats descending: 10 ops
__device__ __forceinline__ void sort4(float x0, float x1, float x2, float x3,
                                      float& a, float& b, float& c, float& d) {
    float p = fmaxf(x0, x1), q = fminf(x0, x1);
    float r = fmaxf(x2, x3), s = fminf(x2, x3);
    a = fmaxf(p, r); float tt = fminf(p, r);
    d = fminf(q, s); float u  = fmaxf(q, s);
    b = fmaxf(tt, u); c = fminf(tt, u);
}
// merge sorted-desc R with sorted-desc A -> top4 desc in R: 12 ops
__device__ __forceinline__ void merge4(float& r0, float& r1, float& r2, float& r3,
                                       float a0, float a1, float a2, float a3) {
    float L0 = fmaxf(r0, a3), L1 = fmaxf(r1, a2);
    float L2 = fmaxf(r2, a1), L3 = fmaxf(r3, a0);
    float m0 = fmaxf(L0, L2), m2 = fminf(L0, L2);
    float m1 = fmaxf(L1, L3), m3 = fminf(L1, L3);
    r0 = fmaxf(m0, m1); r1 = fminf(m0, m1);
    r2 = fmaxf(m2, m3); r3 = fminf(m2, m3);
}
// insert e into sorted-desc top4: 7 ops
__device__ __forceinline__ void top4_push(float e, float& t0, float& t1,
                                          float& t2, float& t3) {
    float c0 = fminf(t0, e);  t0 = fmaxf(t0, e);
    float c1 = fminf(t1, c0); t1 = fmaxf(t1, c0);
    float c2 = fminf(t2, c1); t2 = fmaxf(t2, c1);
    t3 = fmaxf(t3, c2);
}

__global__ __launch_bounds__(TPB, 5)
void lqe_kernel(const float* __restrict__ scores,
                const float* __restrict__ pred,
                const float* __restrict__ w1,
                const float* __restrict__ b1,
                const float* __restrict__ w2,
                const float* __restrict__ b2,
                float* __restrict__ out)
{
    extern __shared__ float smem[];
    float* buf0 = smem;                               // [32][132] tile buffer A
    float* buf1 = smem + BUF_FLOATS;                  // [32][132] tile buffer B
    float* stat = smem + 2 * BUF_FLOATS;              // [32][20] packed stats
    float* wsm  = stat + TILE_POS * STAT_ROW;         // [64][20] folded weights
    float* qs   = wsm + 64 * WROW;                    // [32] per-warp q slots

    const int t  = threadIdx.x;
    const int l  = t & 31;        // lane
    const int w  = t >> 5;        // warp: owns positions w*8 .. w*8+7
    const int sm_pos = l >> 2;    // softmax: local pos in warp (0..7)
    const int sm_sid = l & 3;     // softmax: side
    const int pg = l >> 3;        // MLP: position subgroup (0..3)
    const int rg = l & 7;         // MLP: row group (0..7)
    const int blockStart = blockIdx.x * TPB;
    const float b2v = __ldg(b2);

    const uint32_t buf0u = (uint32_t)__cvta_generic_to_shared(buf0);
    const uint32_t buf1u = (uint32_t)__cvta_generic_to_shared(buf1);
    const float4* g4 = (const float4*)(pred + (size_t)blockStart * DPOS);

    // ---- prologue: start tile 0 copy into buf0 (overlaps weight build) ----
    {
        #pragma unroll
        for (int j = 0; j < 8; j++)
            cp16(buf0u + (uint32_t)(t + j * TPB) * 16u, g4 + t + j * TPB);
        if (t < 32)
            cp16(buf0u + (uint32_t)(t + 8 * TPB) * 16u, g4 + t + 8 * TPB);
        CP_COMMIT();
    }

    // ---- folded weight table: wsm[j][k] ----
    // k<16: w_eff[j][4s+i] = w1[j][5s+i] + 0.25*w1[j][5s+4]; k16=b1[j]; k17=w2[j]
    #pragma unroll
    for (int k = 0; k < (64 * WROW) / TPB; k++) {
        int f   = t + k * TPB;
        int row = f / WROW;
        int cc  = f - row * WROW;
        float v = 0.f;
        if (cc < 16) {
            int ss = cc >> 2, ii = cc & 3;
            v = __ldg(w1 + row * 20 + 5 * ss + ii)
              + 0.25f * __ldg(w1 + row * 20 + 5 * ss + 4);
        } else if (cc == 16) v = __ldg(b1 + row);
        else if (cc == 17)   v = __ldg(w2 + row);
        wsm[f] = v;
    }

    const float4* sc4 = (const float4*)scores + (size_t)blockStart * (NCOUT / 4);
    float4*       ou4 = (float4*)out          + (size_t)blockStart * (NCOUT / 4);
    // softmax row offset inside buffer (scalar reads, CF banks 4*pos+sid+k)
    const int rowOff = (w * 8 + sm_pos) * DPOS + sm_sid * NBINS;
    // out-phase base: warp chunk is 160 f4; lane starts at p0 = l/20
    const int p0 = l / 20;
    const int r0 = l - p0 * 20;

    #pragma unroll
    for (int tau = 0; tau < NTILES; tau++) {
        CP_WAIT0();
        __syncthreads();                       // buf(tau) visible; ONLY barrier

        float* bufC = (tau & 1) ? buf1 : buf0;

        // ---- issue copy(tau+1) NOW into the other buffer (full-tile window) ----
        if (tau < NTILES - 1) {
            uint32_t dstu = (tau & 1) ? buf0u : buf1u;
            const float4* gt = g4 + (tau + 1) * (TILE_POS * NBINS);
            #pragma unroll
            for (int j = 0; j < 8; j++)
                cp16(dstu + (uint32_t)(t + j * TPB) * 16u, gt + t + j * TPB);
            if (t < 32)
                cp16(dstu + (uint32_t)(t + 8 * TPB) * 16u, gt + t + 8 * TPB);
            CP_COMMIT();
        }

        // ---- prefetch this tile's scores for the warp's own chunk ----
        const int cBase = tau * 640 + w * 160;
        float4 rs0 = sc4[cBase + l];
        float4 rs1 = sc4[cBase + l + 32];
        float4 rs2 = sc4[cBase + l + 64];
        float4 rs3 = sc4[cBase + l + 96];
        float4 rs4 = sc4[cBase + l + 128];

        // ---- softmax + top4: quad mapping, 33 scalar CF LDS, no masks ----
        {
            const float* x = bufC + rowOff;
            float r0s, r1s, r2s, r3s;
            float sum0, sum1;
            {
                float e0 = ex2f(x[0] * LOG2E);
                float e1 = ex2f(x[1] * LOG2E);
                float e2 = ex2f(x[2] * LOG2E);
                float e3 = ex2f(x[3] * LOG2E);
                sum0 = e0 + e2; sum1 = e1 + e3;
                sort4(e0, e1, e2, e3, r0s, r1s, r2s, r3s);
            }
            #pragma unroll
            for (int g = 1; g < 8; g++) {
                float e0 = ex2f(x[4 * g + 0] * LOG2E);
                float e1 = ex2f(x[4 * g + 1] * LOG2E);
                float e2 = ex2f(x[4 * g + 2] * LOG2E);
                float e3 = ex2f(x[4 * g + 3] * LOG2E);
                sum0 += e0 + e2; sum1 += e1 + e3;
                float a0, a1, a2, a3;
                sort4(e0, e1, e2, e3, a0, a1, a2, a3);
                merge4(r0s, r1s, r2s, r3s, a0, a1, a2, a3);
            }
            {
                float e = ex2f(x[32] * LOG2E);
                sum0 += e;
                top4_push(e, r0s, r1s, r2s, r3s);
            }
            float inv = rcpf(sum0 + sum1);
            *(float4*)(stat + (w * 8 + sm_pos) * STAT_ROW + 4 * sm_sid) =
                make_float4(r0s * inv, r1s * inv, r2s * inv, r3s * inv);
        }
        __syncwarp();                          // stat is warp-local now

        // ---- MLP: 8 rows (j = rg + 8i) x 2 positions (w8+pg, w8+pg+4) ----
        {
            const ulonglong2* sAr =
                (const ulonglong2*)(stat + (w * 8 + pg) * STAT_ROW);
            const ulonglong2* sBr =
                (const ulonglong2*)(stat + (w * 8 + pg + 4) * STAT_ROW);
            ulonglong2 aA = sAr[0], aB = sAr[1], aC = sAr[2], aD = sAr[3];
            ulonglong2 bA = sBr[0], bB = sBr[1], bC = sBr[2], bD = sBr[3];
            float qA = 0.f, qB = 0.f;
            #pragma unroll
            for (int i = 0; i < 8; i++) {
                int j = rg + 8 * i;            // stride-80B rows: conflict-free
                const ulonglong2* wrow = (const ulonglong2*)(wsm + j * WROW);
                ulonglong2 wa = wrow[0];
                ulonglong2 wb = wrow[1];
                ulonglong2 wc2 = wrow[2];
                ulonglong2 wd = wrow[3];
                float2 bw = *(const float2*)(wsm + j * WROW + 16);

                u64 xA = fma2(wa.x, aA.x, 0ull);
                u64 yA = fma2(wc2.x, aC.x, 0ull);
                u64 xB = fma2(wa.x, bA.x, 0ull);
                u64 yB = fma2(wc2.x, bC.x, 0ull);
                xA = fma2(wa.y, aA.y, xA);  yA = fma2(wc2.y, aC.y, yA);
                xB = fma2(wa.y, bA.y, xB);  yB = fma2(wc2.y, bC.y, yB);
                xA = fma2(wb.x, aB.x, xA);  yA = fma2(wd.x, aD.x, yA);
                xB = fma2(wb.x, bB.x, xB);  yB = fma2(wd.x, bD.x, yB);
                xA = fma2(wb.y, aB.y, xA);  yA = fma2(wd.y, aD.y, yA);
                xB = fma2(wb.y, bB.y, xB);  yB = fma2(wd.y, bD.y, yB);

                u64 sA2 = addf2(xA, yA);
                u64 sB2 = addf2(xB, yB);
                float a0, a1, c0, c1;
                unpack2(sA2, a0, a1);
                unpack2(sB2, c0, c1);
                float hA = (a0 + a1) + bw.x;
                float hB = (c0 + c1) + bw.x;
                hA = fmaxf(hA, 0.f);
                hB = fmaxf(hB, 0.f);
                qA = fmaf(hA, bw.y, qA);
                qB = fmaf(hB, bw.y, qB);
            }
            qA += __shfl_xor_sync(0xffffffffu, qA, 1);
            qB += __shfl_xor_sync(0xffffffffu, qB, 1);
            qA += __shfl_xor_sync(0xffffffffu, qA, 2);
            qB += __shfl_xor_sync(0xffffffffu, qB, 2);
            qA += __shfl_xor_sync(0xffffffffu, qA, 4);
            qB += __shfl_xor_sync(0xffffffffu, qB, 4);
            if (rg == 0) {
                qs[w * 8 + pg]     = qA + b2v;
                qs[w * 8 + pg + 4] = qB + b2v;
            }
        }
        __syncwarp();                          // qs warp-local

        // ---- out-add: warp's contiguous 160-f4 chunk, coalesced ----
        {
            const float* qb = qs + w * 8;
            int pp = p0, r = r0;
            float4 v; float qv;
            qv = qb[pp]; v = rs0;
            v.x += qv; v.y += qv; v.z += qv; v.w += qv;
            ou4[cBase + l] = v;
            r += 12; pp += 1; if (r >= 20) { r -= 20; pp += 1; }
            qv = qb[pp]; v = rs1;
            v.x += qv; v.y += qv; v.z += qv; v.w += qv;
            ou4[cBase + l + 32] = v;
            r += 12; pp += 1; if (r >= 20) { r -= 20; pp += 1; }
            qv = qb[pp]; v = rs2;
            v.x += qv; v.y += qv; v.z += qv; v.w += qv;
            ou4[cBase + l + 64] = v;
            r += 12; pp += 1; if (r >= 20) { r -= 20; pp += 1; }
            qv = qb[pp]; v = rs3;
            v.x += qv; v.y += qv; v.z += qv; v.w += qv;
            ou4[cBase + l + 96] = v;
            r += 12; pp += 1; if (r >= 20) { r -= 20; pp += 1; }
            qv = qb[pp]; v = rs4;
            v.x += qv; v.y += qv; v.z += qv; v.w += qv;
            ou4[cBase + l + 128] = v;
        }
        // no further barriers: all per-tile state (stat, qs) is warp-private;
        // buf hazard is covered by the next tile's top barrier.
    }
}

extern "C" void kernel_launch(void* const* d_in, const int* in_sizes, int n_in,
                              void* d_out, int out_size)
{
    const float* scores = (const float*)d_in[0];
    const float* pred   = (const float*)d_in[1];
    const float* w1     = (const float*)d_in[2];
    const float* b1     = (const float*)d_in[3];
    const float* w2     = (const float*)d_in[4];
    const float* b2     = (const float*)d_in[5];
    // d_in[6] = k_top (fixed 4, compile-time specialized)

    int npos = in_sizes[1] / DPOS;     // 320000
    int grid = npos / TPB;             // 2500 exact

    size_t smem = (size_t)(2 * BUF_FLOATS + TILE_POS * STAT_ROW + 64 * WROW
                           + TILE_POS) * sizeof(float);
    cudaFuncSetAttribute(lqe_kernel, cudaFuncAttributeMaxDynamicSharedMemorySize,
                         (int)smem);
    lqe_kernel<<<grid, TPB, smem>>>(scores, pred, w1, b1, w2, b2, (float*)d_out);
}

// round 16
// speedup vs baseline: 1.0063x; 1.0017x over previous
#include <cuda_runtime.h>
#include <cstdint>

// LQE_17841294147886 — fused softmax/top4/MLP/broadcast-add
// R13: tournament-tree top-4 merge (depth 3 instead of serial chain of 7;
//      same op count, ~2.5x shorter critical path, 8 independent sort4s).
//      Everything else identical to R12 (76.2us base).

#define TPB        128
#define NBINS      33
#define DPOS       132
#define TILE_POS   32
#define NTILES     4
#define BUF_FLOATS (TILE_POS * DPOS)      // 4224 per buffer
#define STAT_ROW   20
#define WROW       20
#define NCOUT      80
#define LOG2E      1.4426950408889634f

typedef unsigned long long u64;

__device__ __forceinline__ u64 fma2(u64 a, u64 b, u64 c) {
    u64 d; asm("fma.rn.f32x2 %0, %1, %2, %3;" : "=l"(d) : "l"(a), "l"(b), "l"(c));
    return d;
}
__device__ __forceinline__ u64 addf2(u64 a, u64 b) {
    u64 d; asm("add.rn.f32x2 %0, %1, %2;" : "=l"(d) : "l"(a), "l"(b));
    return d;
}
__device__ __forceinline__ void unpack2(u64 v, float& lo, float& hi) {
    asm("mov.b64 {%0, %1}, %2;" : "=f"(lo), "=f"(hi) : "l"(v));
}
__device__ __forceinline__ float ex2f(float x) {
    float r; asm("ex2.approx.f32 %0, %1;" : "=f"(r) : "f"(x));
    return r;
}
__device__ __forceinline__ float rcpf(float x) {
    float r; asm("rcp.approx.f32 %0, %1;" : "=f"(r) : "f"(x));
    return r;
}
__device__ __forceinline__ void cp16(uint32_t dst, const void* src) {
    asm volatile("cp.async.cg.shared.global [%0], [%1], 16;"
                 :: "r"(dst), "l"(src));
}
#define CP_COMMIT() asm volatile("cp.async.commit_group;" ::: "memory")
#define CP_WAIT0()  asm volatile("cp.async.wait_group 0;" ::: "memory")

// sort 4 floats descending: 10 ops, depth 3
__device__ __forceinline__ void sort4(float x0, float x1, float x2, float x3,
                                      float& a, float& b, float& c, float& d) {
    float p = fmaxf(x0, x1), q = fminf(x0, x1);
    float r = fmaxf(x2, x3), s = fminf(x2, x3);
    a = fmaxf(p, r); float tt = fminf(p, r);
    d = fminf(q, s); float u  = fmaxf(q, s);
    b = fmaxf(tt, u); c = fminf(tt, u);
}
// merge sorted-desc R with sorted-desc A -> top4 desc in R: 12 ops, depth 3
__device__ __forceinline__ void merge4(float& r0, float& r1, float& r2, float& r3,
                                       float a0, float a1, float a2, float a3) {
    float L0 = fmaxf(r0, a3), L1 = fmaxf(r1, a2);
    float L2 = fmaxf(r2, a1), L3 = fmaxf(r3, a0);
    float m0 = fmaxf(L0, L2), m2 = fminf(L0, L2);
    float m1 = fmaxf(L1, L3), m3 = fminf(L1, L3);
    r0 = fmaxf(m0, m1); r1 = fminf(m0, m1);
    r2 = fmaxf(m2, m3); r3 = fminf(m2, m3);
}
// insert e into sorted-desc top4: 7 ops
__device__ __forceinline__ void top4_push(float e, float& t0, float& t1,
                                          float& t2, float& t3) {
    float c0 = fminf(t0, e);  t0 = fmaxf(t0, e);
    float c1 = fminf(t1, c0); t1 = fmaxf(t1, c0);
    float c2 = fminf(t2, c1); t2 = fmaxf(t2, c1);
    t3 = fmaxf(t3, c2);
}
// load group g (4 floats), exp, sort: returns sorted desc + adds to sums
__device__ __forceinline__ void group_exp_sort(const float* x, int g,
                                               float& s0, float& s1,
                                               float& a, float& b,
                                               float& c, float& d) {
    float e0 = ex2f(x[4 * g + 0] * LOG2E);
    float e1 = ex2f(x[4 * g + 1] * LOG2E);
    float e2 = ex2f(x[4 * g + 2] * LOG2E);
    float e3 = ex2f(x[4 * g + 3] * LOG2E);
    s0 += e0 + e2; s1 += e1 + e3;
    sort4(e0, e1, e2, e3, a, b, c, d);
}

__global__ __launch_bounds__(TPB, 5)
void lqe_kernel(const float* __restrict__ scores,
                const float* __restrict__ pred,
                const float* __restrict__ w1,
                const float* __restrict__ b1,
                const float* __restrict__ w2,
                const float* __restrict__ b2,
                float* __restrict__ out)
{
    extern __shared__ float smem[];
    float* buf0 = smem;                               // [32][132] tile buffer A
    float* buf1 = smem + BUF_FLOATS;                  // [32][132] tile buffer B
    float* stat = smem + 2 * BUF_FLOATS;              // [32][20] packed stats
    float* wsm  = stat + TILE_POS * STAT_ROW;         // [64][20] folded weights
    float* qs   = wsm + 64 * WROW;                    // [32] per-warp q slots

    const int t  = threadIdx.x;
    const int l  = t & 31;        // lane
    const int w  = t >> 5;        // warp: owns positions w*8 .. w*8+7
    const int sm_pos = l >> 2;    // softmax: local pos in warp (0..7)
    const int sm_sid = l & 3;     // softmax: side
    const int pg = l >> 3;        // MLP: position subgroup (0..3)
    const int rg = l & 7;         // MLP: row group (0..7)
    const int blockStart = blockIdx.x * TPB;
    const float b2v = __ldg(b2);

    const uint32_t buf0u = (uint32_t)__cvta_generic_to_shared(buf0);
    const uint32_t buf1u = (uint32_t)__cvta_generic_to_shared(buf1);
    const float4* g4 = (const float4*)(pred + (size_t)blockStart * DPOS);

    // ---- prologue: start tile 0 copy into buf0 (overlaps weight build) ----
    {
        #pragma unroll
        for (int j = 0; j < 8; j++)
            cp16(buf0u + (uint32_t)(t + j * TPB) * 16u, g4 + t + j * TPB);
        if (t < 32)
            cp16(buf0u + (uint32_t)(t + 8 * TPB) * 16u, g4 + t + 8 * TPB);
        CP_COMMIT();
    }

    // ---- folded weight table: wsm[j][k] ----
    // k<16: w_eff[j][4s+i] = w1[j][5s+i] + 0.25*w1[j][5s+4]; k16=b1[j]; k17=w2[j]
    #pragma unroll
    for (int k = 0; k < (64 * WROW) / TPB; k++) {
        int f   = t + k * TPB;
        int row = f / WROW;
        int cc  = f - row * WROW;
        float v = 0.f;
        if (cc < 16) {
            int ss = cc >> 2, ii = cc & 3;
            v = __ldg(w1 + row * 20 + 5 * ss + ii)
              + 0.25f * __ldg(w1 + row * 20 + 5 * ss + 4);
        } else if (cc == 16) v = __ldg(b1 + row);
        else if (cc == 17)   v = __ldg(w2 + row);
        wsm[f] = v;
    }

    const float4* sc4 = (const float4*)scores + (size_t)blockStart * (NCOUT / 4);
    float4*       ou4 = (float4*)out          + (size_t)blockStart * (NCOUT / 4);
    // softmax row offset inside buffer (scalar reads, CF banks 4*pos+sid+k)
    const int rowOff = (w * 8 + sm_pos) * DPOS + sm_sid * NBINS;
    // out-phase base: warp chunk is 160 f4; lane starts at p0 = l/20
    const int p0 = l / 20;
    const int r0 = l - p0 * 20;

    #pragma unroll
    for (int tau = 0; tau < NTILES; tau++) {
        CP_WAIT0();
        __syncthreads();                       // buf(tau) visible; ONLY barrier

        float* bufC = (tau & 1) ? buf1 : buf0;

        // ---- issue copy(tau+1) NOW into the other buffer (full-tile window) ----
        if (tau < NTILES - 1) {
            uint32_t dstu = (tau & 1) ? buf0u : buf1u;
            const float4* gt = g4 + (tau + 1) * (TILE_POS * NBINS);
            #pragma unroll
            for (int j = 0; j < 8; j++)
                cp16(dstu + (uint32_t)(t + j * TPB) * 16u, gt + t + j * TPB);
            if (t < 32)
                cp16(dstu + (uint32_t)(t + 8 * TPB) * 16u, gt + t + 8 * TPB);
            CP_COMMIT();
        }

        // ---- prefetch this tile's scores for the warp's own chunk ----
        const int cBase = tau * 640 + w * 160;
        float4 rs0 = sc4[cBase + l];
        float4 rs1 = sc4[cBase + l + 32];
        float4 rs2 = sc4[cBase + l + 64];
        float4 rs3 = sc4[cBase + l + 96];
        float4 rs4 = sc4[cBase + l + 128];

        // ---- softmax + top4: tournament tree (depth 3), 33 scalar CF LDS ----
        {
            const float* x = bufC + rowOff;
            float sum0 = 0.f, sum1 = 0.f;

            // half A: groups 0..3
            float A0, A1, A2, A3, u0, u1, u2, u3;
            group_exp_sort(x, 0, sum0, sum1, A0, A1, A2, A3);
            group_exp_sort(x, 1, sum0, sum1, u0, u1, u2, u3);
            merge4(A0, A1, A2, A3, u0, u1, u2, u3);          // g0·g1
            float B0, B1, B2, B3;
            group_exp_sort(x, 2, sum0, sum1, B0, B1, B2, B3);
            group_exp_sort(x, 3, sum0, sum1, u0, u1, u2, u3);
            merge4(B0, B1, B2, B3, u0, u1, u2, u3);          // g2·g3
            merge4(A0, A1, A2, A3, B0, B1, B2, B3);          // half A

            // half B: groups 4..7
            float C0, C1, C2, C3;
            group_exp_sort(x, 4, sum0, sum1, C0, C1, C2, C3);
            group_exp_sort(x, 5, sum0, sum1, u0, u1, u2, u3);
            merge4(C0, C1, C2, C3, u0, u1, u2, u3);          // g4·g5
            float D0, D1, D2, D3;
            group_exp_sort(x, 6, sum0, sum1, D0, D1, D2, D3);
            group_exp_sort(x, 7, sum0, sum1, u0, u1, u2, u3);
            merge4(D0, D1, D2, D3, u0, u1, u2, u3);          // g6·g7
            merge4(C0, C1, C2, C3, D0, D1, D2, D3);          // half B

            merge4(A0, A1, A2, A3, C0, C1, C2, C3);          // final

            float e32 = ex2f(x[32] * LOG2E);
            sum0 += e32;
            top4_push(e32, A0, A1, A2, A3);

            float inv = rcpf(sum0 + sum1);
            *(float4*)(stat + (w * 8 + sm_pos) * STAT_ROW + 4 * sm_sid) =
                make_float4(A0 * inv, A1 * inv, A2 * inv, A3 * inv);
        }
        __syncwarp();                          // stat is warp-local

        // ---- MLP: 8 rows (j = rg + 8i) x 2 positions (w8+pg, w8+pg+4) ----
        {
            const ulonglong2* sAr =
                (const ulonglong2*)(stat + (w * 8 + pg) * STAT_ROW);
            const ulonglong2* sBr =
                (const ulonglong2*)(stat + (w * 8 + pg + 4) * STAT_ROW);
            ulonglong2 aA = sAr[0], aB = sAr[1], aC = sAr[2], aD = sAr[3];
            ulonglong2 bA = sBr[0], bB = sBr[1], bC = sBr[2], bD = sBr[3];
            float qA = 0.f, qB = 0.f;
            #pragma unroll
            for (int i = 0; i < 8; i++) {
                int j = rg + 8 * i;            // stride-80B rows: conflict-free
                const ulonglong2* wrow = (const ulonglong2*)(wsm + j * WROW);
                ulonglong2 wa = wrow[0];
                ulonglong2 wb = wrow[1];
                ulonglong2 wc2 = wrow[2];
                ulonglong2 wd = wrow[3];
                float2 bw = *(const float2*)(wsm + j * WROW + 16);

                u64 xA = fma2(wa.x, aA.x, 0ull);
                u64 yA = fma2(wc2.x, aC.x, 0ull);
                u64 xB = fma2(wa.x, bA.x, 0ull);
                u64 yB = fma2(wc2.x, bC.x, 0ull);
                xA = fma2(wa.y, aA.y, xA);  yA = fma2(wc2.y, aC.y, yA);
                xB = fma2(wa.y, bA.y, xB);  yB = fma2(wc2.y, bC.y, yB);
                xA = fma2(wb.x, aB.x, xA);  yA = fma2(wd.x, aD.x, yA);
                xB = fma2(wb.x, bB.x, xB);  yB = fma2(wd.x, bD.x, yB);
                xA = fma2(wb.y, aB.y, xA);  yA = fma2(wd.y, aD.y, yA);
                xB = fma2(wb.y, bB.y, xB);  yB = fma2(wd.y, bD.y, yB);

                u64 sA2 = addf2(xA, yA);
                u64 sB2 = addf2(xB, yB);
                float a0, a1, c0, c1;
                unpack2(sA2, a0, a1);
                unpack2(sB2, c0, c1);
                float hA = (a0 + a1) + bw.x;
                float hB = (c0 + c1) + bw.x;
                hA = fmaxf(hA, 0.f);
                hB = fmaxf(hB, 0.f);
                qA = fmaf(hA, bw.y, qA);
                qB = fmaf(hB, bw.y, qB);
            }
            qA += __shfl_xor_sync(0xffffffffu, qA, 1);
            qB += __shfl_xor_sync(0xffffffffu, qB, 1);
            qA += __shfl_xor_sync(0xffffffffu, qA, 2);
            qB += __shfl_xor_sync(0xffffffffu, qB, 2);
            qA += __shfl_xor_sync(0xffffffffu, qA, 4);
            qB += __shfl_xor_sync(0xffffffffu, qB, 4);
            if (rg == 0) {
                qs[w * 8 + pg]     = qA + b2v;
                qs[w * 8 + pg + 4] = qB + b2v;
            }
        }
        __syncwarp();                          // qs warp-local

        // ---- out-add: warp's contiguous 160-f4 chunk, coalesced ----
        {
            const float* qb = qs + w * 8;
            int pp = p0, r = r0;
            float4 v; float qv;
            qv = qb[pp]; v = rs0;
            v.x += qv; v.y += qv; v.z += qv; v.w += qv;
            ou4[cBase + l] = v;
            r += 12; pp += 1; if (r >= 20) { r -= 20; pp += 1; }
            qv = qb[pp]; v = rs1;
            v.x += qv; v.y += qv; v.z += qv; v.w += qv;
            ou4[cBase + l + 32] = v;
            r += 12; pp += 1; if (r >= 20) { r -= 20; pp += 1; }
            qv = qb[pp]; v = rs2;
            v.x += qv; v.y += qv; v.z += qv; v.w += qv;
            ou4[cBase + l + 64] = v;
            r += 12; pp += 1; if (r >= 20) { r -= 20; pp += 1; }
            qv = qb[pp]; v = rs3;
            v.x += qv; v.y += qv; v.z += qv; v.w += qv;
            ou4[cBase + l + 96] = v;
            r += 12; pp += 1; if (r >= 20) { r -= 20; pp += 1; }
            qv = qb[pp]; v = rs4;
            v.x += qv; v.y += qv; v.z += qv; v.w += qv;
            ou4[cBase + l + 128] = v;
        }
    }
}

extern "C" void kernel_launch(void* const* d_in, const int* in_sizes, int n_in,
                              void* d_out, int out_size)
{
    const float* scores = (const float*)d_in[0];
    const float* pred   = (const float*)d_in[1];
    const float* w1     = (const float*)d_in[2];
    const float* b1     = (const float*)d_in[3];
    const float* w2     = (const float*)d_in[4];
    const float* b2     = (const float*)d_in[5];
    // d_in[6] = k_top (fixed 4, compile-time specialized)

    int npos = in_sizes[1] / DPOS;     // 320000
    int grid = npos / TPB;             // 2500 exact

    size_t smem = (size_t)(2 * BUF_FLOATS + TILE_POS * STAT_ROW + 64 * WROW
                           + TILE_POS) * sizeof(float);
    cudaFuncSetAttribute(lqe_kernel, cudaFuncAttributeMaxDynamicSharedMemorySize,
                         (int)smem);
    lqe_kernel<<<grid, TPB, smem>>>(scores, pred, w1, b1, w2, b2, (float*)d_out);
}